// round 3
// baseline (speedup 1.0000x reference)
#include <cuda_runtime.h>
#include <cuda_bf16.h>
#include <math.h>

// HierarchicalDistanceLoss, fused single kernel:
//   ce[b]  = logsumexp(logits[b,:]) - logits[b, labels[b]]
//   pred   = argmax(logits[b,:]) (first max)
//   df[b]  = dis_matrix[labels[b], pred] + 0.5
//   out[0] = mean(ce*df), out[1..B] = df
//
// R3 changes vs R2:
//  - tile read from smem ONCE into a 40-float register array (halves LDS wf;
//    kernel was L1tex-port co-limited)
//  - final mean fused via last-block-done pattern (kills 4.9us finish kernel)

#define CCOLS 40
#define RPB   256            // rows per block == threads per block
#define F4_PER_ROW 10        // 40 floats
#define PAD_F4     11        // padded row length in float4 (conflict-free LDS.128)

__device__ float    g_partials[8192];
__device__ unsigned g_count;          // zero-initialized; self-resets each launch

__global__ void __launch_bounds__(RPB, 4) hier_loss_fused(
    const float4* __restrict__ logits4,   // [B*10] float4
    const int*    __restrict__ labels,    // [B]
    const float*  __restrict__ dis,       // [40*40]
    float*        __restrict__ out,       // [0] = loss (written by last block)
    float*        __restrict__ df_out,    // [B]
    float invB, int nb)
{
    __shared__ float4 tile[RPB * PAD_F4];   // 45056 B
    __shared__ float  wsum[8];
    __shared__ int    isLast;

    const int tid = threadIdx.x;
    const long long blk = blockIdx.x;

    // ---- coalesced global load -> padded smem ----
    const float4* g = logits4 + blk * (RPB * F4_PER_ROW);
    #pragma unroll
    for (int it = 0; it < F4_PER_ROW; ++it) {
        int idx = it * RPB + tid;            // consecutive per warp -> 4 lines/LDG.128
        int row = idx / F4_PER_ROW;
        int s   = idx - row * F4_PER_ROW;
        tile[row * PAD_F4 + s] = g[idx];
    }
    __syncthreads();

    // ---- single smem read of own row into registers ----
    const float4* r  = tile + tid * PAD_F4;
    const float*  rf = (const float*)r;
    float v[CCOLS];
    #pragma unroll
    for (int i = 0; i < F4_PER_ROW; ++i) {
        float4 q = r[i];
        v[4*i+0] = q.x; v[4*i+1] = q.y; v[4*i+2] = q.z; v[4*i+3] = q.w;
    }

    // pass 1 (regs): max + argmax, strict > keeps first occurrence
    float m = v[0];
    int   am = 0;
    #pragma unroll
    for (int j = 1; j < CCOLS; ++j)
        if (v[j] > m) { m = v[j]; am = j; }

    // pass 2 (regs): sum of exp(x - m)
    float s = 0.0f;
    #pragma unroll
    for (int j = 0; j < CCOLS; ++j)
        s += __expf(v[j] - m);
    const float lse = m + __logf(s);

    const long long rowg = blk * RPB + tid;
    const int lab = labels[rowg];
    const float xl = rf[lab];                 // dynamic index -> smem, not regs
    const float ce = lse - xl;

    const float dfv = __ldg(&dis[lab * CCOLS + am]) + 0.5f;
    df_out[rowg] = dfv;

    // ---- deterministic block reduction of ce*df ----
    float c = ce * dfv;
    #pragma unroll
    for (int o = 16; o > 0; o >>= 1)
        c += __shfl_down_sync(0xffffffffu, c, o);
    if ((tid & 31) == 0) wsum[tid >> 5] = c;
    __syncthreads();
    if (tid < 32) {
        float w = (tid < 8) ? wsum[tid] : 0.0f;
        #pragma unroll
        for (int o = 4; o > 0; o >>= 1)
            w += __shfl_down_sync(0xffffffffu, w, o);
        if (tid == 0) g_partials[blockIdx.x] = w;
    }

    // ---- last-block-done final reduction (deterministic order) ----
    if (tid == 0) {
        __threadfence();
        isLast = (atomicAdd(&g_count, 1u) == (unsigned)(nb - 1));
    }
    __syncthreads();
    if (isLast) {
        float acc = 0.0f;
        for (int i = tid; i < nb; i += RPB)
            acc += g_partials[i];
        #pragma unroll
        for (int o = 16; o > 0; o >>= 1)
            acc += __shfl_down_sync(0xffffffffu, acc, o);
        if ((tid & 31) == 0) wsum[tid >> 5] = acc;
        __syncthreads();
        if (tid < 32) {
            float w = (tid < 8) ? wsum[tid] : 0.0f;
            #pragma unroll
            for (int o = 4; o > 0; o >>= 1)
                w += __shfl_down_sync(0xffffffffu, w, o);
            if (tid == 0) {
                out[0] = w * invB;     // mean, NORMALISE = 1
                g_count = 0;           // reset for graph replay
            }
        }
    }
}

extern "C" void kernel_launch(void* const* d_in, const int* in_sizes, int n_in,
                              void* d_out, int out_size)
{
    const float* logits = (const float*)d_in[0];
    const int*   labels = (const int*)d_in[1];
    const float* dis    = (const float*)d_in[2];
    float* out = (float*)d_out;

    const long long B = (long long)in_sizes[1];     // 1048576
    const int nb = (int)(B / RPB);                  // 4096

    // output layout: [loss, df[0..B-1]] if out_size == B+1, else just df
    const int off = out_size - (int)B;
    float* dfo = out + (off > 0 ? off : 0);

    hier_loss_fused<<<nb, RPB>>>((const float4*)logits, labels, dis,
                                 out, dfo, 1.0f / (float)B, nb);
}